// round 10
// baseline (speedup 1.0000x reference)
#include <cuda_runtime.h>
#include <cuda_bf16.h>
#include <cstdint>

#define Bn 8
#define Nn 4096
#define En 65536
#define Dn 256
#define M_TOT (Bn*Nn)   // 32768 rows
#define SLOTS 96        // per-target src-list capacity (deg ~ Binom(65536,1/4096), mean 16)

// Scratch (allocation-free rule: __device__ globals)
__device__ float g_h[(size_t)M_TOT * Dn];          // 33.5 MB: h = X W^T + b
__device__ int   g_cur[M_TOT];                     // per-(b,tgt) active-edge count
__device__ int   g_csr[(size_t)M_TOT * SLOTS];     // src lists, fixed stride

// ---------------------------------------------------------------------------
// TF32 helpers. mma.sync m16n8k8 tf32 (sm_80+) and ldmatrix (sm_75+) are
// plain PTX -- no 'a' gating -- so they survive the compute_103 target.
// ---------------------------------------------------------------------------
__device__ __forceinline__ uint32_t tf32_rna_u(float x) {
    uint32_t u;
    asm("cvt.rna.tf32.f32 %0, %1;" : "=r"(u) : "f"(x));
    return u;
}
__device__ __forceinline__ uint32_t smem_u32(const void* p) {
    uint32_t a;
    asm("{ .reg .u64 t; cvta.to.shared.u64 t, %1; cvt.u32.u64 %0, t; }"
        : "=r"(a) : "l"(p));
    return a;
}

#define LDSM4(r, a) \
    asm volatile("ldmatrix.sync.aligned.m8n8.x4.shared.b16 {%0,%1,%2,%3}, [%4];" \
        : "=r"((r)[0]), "=r"((r)[1]), "=r"((r)[2]), "=r"((r)[3]) : "r"(a))

#define MMA_TF32(c, A, b0, b1) \
    asm volatile("mma.sync.aligned.m16n8k8.row.col.f32.tf32.tf32.f32 " \
        "{%0,%1,%2,%3}, {%4,%5,%6,%7}, {%8,%9}, {%0,%1,%2,%3};" \
        : "+f"((c)[0]), "+f"((c)[1]), "+f"((c)[2]), "+f"((c)[3]) \
        : "r"((A)[0]), "r"((A)[1]), "r"((A)[2]), "r"((A)[3]), \
          "r"(b0), "r"(b1))

// split a raw fp32 register (held as u32) into tf32 hi/lo
__device__ __forceinline__ void split_tf32(uint32_t raw, uint32_t& hi, uint32_t& lo) {
    const float v = __uint_as_float(raw);
    hi = tf32_rna_u(v);
    lo = tf32_rna_u(v - __uint_as_float(hi));
}

// ---------------------------------------------------------------------------
// Kernel 1: GEMM h[m,o] = sum_i X[m,i]*W[o,i] + bias[o], tensor-core tf32,
// fp32-accurate 3-pass split (hi*hi + hi*lo + lo*hi), split done IN REGISTERS
// after ldmatrix of the raw fp32 tiles -> half the smem traffic of r7.
// CTA 128(M) x 64(N), 8 warps of 32x32, BK=16 double-buffered.
// LDA=20 -> conflict-free LDSM rows. Epilogue zeroes g_cur.
// ---------------------------------------------------------------------------
#define LDA  20                  // smem row stride in floats
#define BOFF (128 * LDA)         // B tile after 128 A rows
#define SSZ  (192 * LDA)         // floats per stage (A 128 rows + B 64 rows)
#define GEMM_SMEM (2 * SSZ * 4)  // 30720 bytes

__global__ __launch_bounds__(256, 2) void gemm_mma_kernel(const float* __restrict__ X,
                                                          const float* __restrict__ W,
                                                          const float* __restrict__ bias) {
    extern __shared__ __align__(16) float sm[];
    const uint32_t sbase = smem_u32(sm);
    const int tid  = threadIdx.x;
    const int wid  = tid >> 5;
    const int lane = tid & 31;
    const int gid  = lane >> 2;        // group of 4 (epilogue row)
    const int tig  = lane & 3;         // thread in group (epilogue col)
    const int warp_m = wid & 3;        // 4 x 32 rows
    const int warp_n = wid >> 2;       // 2 x 32 cols
    const int bm = blockIdx.x * 128;
    const int bn = blockIdx.y * 64;

    float c[2][4][4] = {};             // 2 m-tiles x 4 n-tiles x 4 accum

    // ldmatrix per-lane row assignments (word offsets within a stage)
    const int a_row_in = ((lane >> 3) & 1) * 8 + (lane & 7);
    const int a_kh     = (lane >> 4) * 4;          // k-half * 4
    int a_off[2], b_off[2];
    #pragma unroll
    for (int mt = 0; mt < 2; mt++)
        a_off[mt] = (warp_m * 32 + mt * 16 + a_row_in) * LDA + a_kh;
    const int b_q   = lane >> 3;
    const int b_kh  = (b_q & 1) * 4;
    const int b_sub = (b_q >> 1) & 1;
    #pragma unroll
    for (int p = 0; p < 2; p++)
        b_off[p] = BOFF + (warp_n * 32 + p * 16 + b_sub * 8 + (lane & 7)) * LDA + b_kh;

    float4 xa[2], wb;
    auto loadg = [&](int k0) {
        #pragma unroll
        for (int i = 0; i < 2; i++) {
            const int f = tid + i * 256;           // 0..511
            const int r = f >> 2, k4 = (f & 3) << 2;
            xa[i] = *(const float4*)&X[(size_t)(bm + r) * Dn + k0 + k4];
        }
        const int r = tid >> 2, k4 = (tid & 3) << 2;
        wb = *(const float4*)&W[(size_t)(bn + r) * Dn + k0 + k4];
    };
    auto stores = [&](int buf) {       // raw fp32 staging, 3 STS.128/thread
        float* base = sm + buf * SSZ;
        #pragma unroll
        for (int i = 0; i < 2; i++) {
            const int f = tid + i * 256;
            const int r = f >> 2, k4 = (f & 3) << 2;
            *(float4*)&base[r * LDA + k4] = xa[i];
        }
        const int r = tid >> 2, k4 = (tid & 3) << 2;
        *(float4*)&base[BOFF + r * LDA + k4] = wb;
    };

    loadg(0);
    stores(0);
    __syncthreads();

    #pragma unroll 1
    for (int t = 0; t < Dn / 16; t++) {
        const int buf = t & 1;
        if (t < Dn / 16 - 1) loadg((t + 1) * 16);
        const uint32_t sb = sbase + (uint32_t)buf * (SSZ * 4);

        #pragma unroll
        for (int kk = 0; kk < 2; kk++) {
            const int kc = kk * 8;
            uint32_t ar[2][4], br[2][4];
            #pragma unroll
            for (int mt = 0; mt < 2; mt++) LDSM4(ar[mt], sb + (a_off[mt] + kc) * 4);
            #pragma unroll
            for (int p = 0; p < 2; p++)    LDSM4(br[p],  sb + (b_off[p]  + kc) * 4);

            uint32_t ah[2][4], al[2][4], bh[2][4], bl[2][4];
            #pragma unroll
            for (int mt = 0; mt < 2; mt++)
                #pragma unroll
                for (int j = 0; j < 4; j++) split_tf32(ar[mt][j], ah[mt][j], al[mt][j]);
            #pragma unroll
            for (int p = 0; p < 2; p++)
                #pragma unroll
                for (int j = 0; j < 4; j++) split_tf32(br[p][j], bh[p][j], bl[p][j]);

            #pragma unroll
            for (int n = 0; n < 4; n++) {
                const int p = n >> 1, o = (n & 1) * 2;
                #pragma unroll
                for (int m = 0; m < 2; m++) {
                    MMA_TF32(c[m][n], ah[m], bh[p][o], bh[p][o + 1]);   // hi*hi
                    MMA_TF32(c[m][n], ah[m], bl[p][o], bl[p][o + 1]);   // hi*lo
                    MMA_TF32(c[m][n], al[m], bh[p][o], bh[p][o + 1]);   // lo*hi
                }
            }
        }

        if (t < Dn / 16 - 1) stores(buf ^ 1);
        __syncthreads();
    }

    // Epilogue: bias add, store h (float2 per fragment row-pair)
    #pragma unroll
    for (int m = 0; m < 2; m++) {
        const int r0 = bm + warp_m * 32 + m * 16 + gid;
        #pragma unroll
        for (int n = 0; n < 4; n++) {
            const int cc = bn + warp_n * 32 + n * 8 + 2 * tig;
            const float b0 = bias[cc], b1 = bias[cc + 1];
            *(float2*)&g_h[(size_t)r0 * Dn + cc] =
                make_float2(c[m][n][0] + b0, c[m][n][1] + b1);
            *(float2*)&g_h[(size_t)(r0 + 8) * Dn + cc] =
                make_float2(c[m][n][2] + b0, c[m][n][3] + b1);
        }
    }

    // zero CSR cursors: 1024 blocks x 32 ints = 32768
    const int lb = blockIdx.y * 256 + blockIdx.x;   // 0..1023
    if (tid < 32) g_cur[lb * 32 + tid] = 0;
}

// ---------------------------------------------------------------------------
// Edge-index dtype sniffing (int64 vs int32): values < 4096, so int64 data has
// all odd int32 words == 0. 16 checks -> misclassification prob ~4096^-16.
// ---------------------------------------------------------------------------
__device__ __forceinline__ bool ei_is_int64(const int* p) {
    int acc = 0;
    #pragma unroll
    for (int i = 0; i < 16; i++) acc |= p[2 * i + 1];
    return acc == 0;
}
__device__ __forceinline__ void load_edge(const void* ei, int b, int e,
                                          bool is64, int& src, int& tgt) {
    if (is64) {
        const long long* base = (const long long*)ei + (size_t)b * 2 * En;
        src = (int)base[e];
        tgt = (int)base[En + e];
    } else {
        const int* base = (const int*)ei + (size_t)b * 2 * En;
        src = base[e];
        tgt = base[En + e];
    }
}

// ---------------------------------------------------------------------------
// Kernel 2: single-pass CSR build. Active edge -> slot in fixed-stride list.
// ---------------------------------------------------------------------------
__global__ __launch_bounds__(256) void edge_kernel(const void* __restrict__ ei,
                                                   const int* __restrict__ nm) {
    const int gid = blockIdx.x * 256 + threadIdx.x;
    if (gid >= Bn * En) return;
    const int b = gid >> 16, e = gid & (En - 1);
    const bool is64 = ei_is_int64((const int*)ei);
    int src, tgt;
    load_edge(ei, b, e, is64, src, tgt);
    if (nm[b * Nn + src] && nm[b * Nn + tgt]) {
        const int row = b * Nn + tgt;
        const int slot = atomicAdd(&g_cur[row], 1);
        if (slot < SLOTS) g_csr[(size_t)row * SLOTS + slot] = src;
    }
}

// ---------------------------------------------------------------------------
// Kernel 3: fused gather + add + LayerNorm + relu + mask.
// 4 rows per 256-thread block; each 64-thread group owns one row,
// each thread 4 columns (float4 loads). Common __syncthreads path.
// ---------------------------------------------------------------------------
__global__ __launch_bounds__(256) void gather_ln_kernel(const float* __restrict__ gamma,
                                                        const float* __restrict__ beta,
                                                        const int* __restrict__ nm,
                                                        float* __restrict__ out) {
    const int tid = threadIdx.x;
    const int grp = tid >> 6;            // 0..3 (row group)
    const int gt  = tid & 63;            // thread in group
    const int row = blockIdx.x * 4 + grp;
    const int c4  = gt * 4;
    const size_t off = (size_t)row * Dn + c4;
    const bool active = nm[row] != 0;

    float4 y = make_float4(0.f, 0.f, 0.f, 0.f);
    if (active) {
        int cnt = g_cur[row];
        cnt = cnt < SLOTS ? cnt : SLOTS;            // memory-safety clamp
        const int* lst = g_csr + (size_t)row * SLOTS;
        const int bbase = (row >> 12) << 12;        // b * Nn
        const float* hb = g_h + (size_t)bbase * Dn + c4;

        float4 a0 = y, a1 = y, a2 = y, a3 = y;
        int i = 0;
        for (; i + 4 <= cnt; i += 4) {              // 4 float4 loads in flight
            const int s0 = lst[i], s1 = lst[i + 1], s2 = lst[i + 2], s3 = lst[i + 3];
            const float4 v0 = *(const float4*)&hb[(size_t)s0 * Dn];
            const float4 v1 = *(const float4*)&hb[(size_t)s1 * Dn];
            const float4 v2 = *(const float4*)&hb[(size_t)s2 * Dn];
            const float4 v3 = *(const float4*)&hb[(size_t)s3 * Dn];
            a0.x += v0.x; a0.y += v0.y; a0.z += v0.z; a0.w += v0.w;
            a1.x += v1.x; a1.y += v1.y; a1.z += v1.z; a1.w += v1.w;
            a2.x += v2.x; a2.y += v2.y; a2.z += v2.z; a2.w += v2.w;
            a3.x += v3.x; a3.y += v3.y; a3.z += v3.z; a3.w += v3.w;
        }
        for (; i < cnt; i++) {
            const float4 v = *(const float4*)&hb[(size_t)lst[i] * Dn];
            a0.x += v.x; a0.y += v.y; a0.z += v.z; a0.w += v.w;
        }
        const float4 hq = *(const float4*)&g_h[off];
        y.x = hq.x + (a0.x + a1.x + a2.x + a3.x) * 0.015625f;   // 1/sqrt(4096)
        y.y = hq.y + (a0.y + a1.y + a2.y + a3.y) * 0.015625f;
        y.z = hq.z + (a0.z + a1.z + a2.z + a3.z) * 0.015625f;
        y.w = hq.w + (a0.w + a1.w + a2.w + a3.w) * 0.015625f;
    }

    // group reduction (2 warps of 32): sum and sumsq over the 256 columns
    float s = y.x + y.y + y.z + y.w;
    float q = y.x * y.x + y.y * y.y + y.z * y.z + y.w * y.w;
    #pragma unroll
    for (int o = 16; o > 0; o >>= 1) {
        s += __shfl_xor_sync(0xFFFFFFFF, s, o);
        q += __shfl_xor_sync(0xFFFFFFFF, q, o);
    }
    __shared__ float s_s[8], s_q[8];
    const int warp_in_blk = tid >> 5;               // 0..7
    if ((tid & 31) == 0) { s_s[warp_in_blk] = s; s_q[warp_in_blk] = q; }
    __syncthreads();
    const float ts = s_s[grp * 2] + s_s[grp * 2 + 1];
    const float tq = s_q[grp * 2] + s_q[grp * 2 + 1];

    float4 o4 = make_float4(0.f, 0.f, 0.f, 0.f);
    if (active) {
        const float mu  = ts * (1.f / Dn);
        const float var = tq * (1.f / Dn) - mu * mu;
        const float r   = rsqrtf(var + 1e-5f);
        const float4 gm = *(const float4*)&gamma[c4];
        const float4 bt = *(const float4*)&beta[c4];
        o4.x = fmaxf((y.x - mu) * r * gm.x + bt.x, 0.f);
        o4.y = fmaxf((y.y - mu) * r * gm.y + bt.y, 0.f);
        o4.z = fmaxf((y.z - mu) * r * gm.z + bt.z, 0.f);
        o4.w = fmaxf((y.w - mu) * r * gm.w + bt.w, 0.f);
    }
    *(float4*)&out[off] = o4;
}

// ---------------------------------------------------------------------------
extern "C" void kernel_launch(void* const* d_in, const int* in_sizes, int n_in,
                              void* d_out, int out_size) {
    const float* X     = (const float*)d_in[0];   // (B,N,D)
    const float* W     = (const float*)d_in[1];   // (D,D)
    const float* bias  = (const float*)d_in[2];   // (D,)
    const float* gamma = (const float*)d_in[3];   // (D,)
    const float* beta  = (const float*)d_in[4];   // (D,)
    const void*  ei    = d_in[5];                 // (B,2,E) int32 or int64
    const int*   nm    = (const int*)d_in[6];     // (B,N) int32
    float*       out   = (float*)d_out;           // (B,N,D) f32

    cudaFuncSetAttribute(gemm_mma_kernel,
                         cudaFuncAttributeMaxDynamicSharedMemorySize, GEMM_SMEM);

    dim3 gg(M_TOT / 128, Dn / 64);                // (256, 4)
    gemm_mma_kernel<<<gg, 256, GEMM_SMEM>>>(X, W, bias);  // also zeroes g_cur

    edge_kernel<<<(Bn * En) / 256, 256>>>(ei, nm);

    gather_ln_kernel<<<M_TOT / 4, 256>>>(gamma, beta, nm, out);
}

// round 11
// speedup vs baseline: 1.3819x; 1.3819x over previous
#include <cuda_runtime.h>
#include <cuda_bf16.h>
#include <cstdint>

#define Bn 8
#define Nn 4096
#define En 65536
#define Dn 256
#define M_TOT (Bn*Nn)   // 32768 rows
#define SLOTS 96        // per-target src-list capacity (deg ~ Binom(65536,1/4096), mean 16)

// Scratch (allocation-free rule: __device__ globals)
__device__ float g_h[(size_t)M_TOT * Dn];          // 33.5 MB: h = X W^T + b
__device__ int   g_cur[M_TOT];                     // per-(b,tgt) active-edge count
__device__ int   g_csr[(size_t)M_TOT * SLOTS];     // src lists, fixed stride

// ---------------------------------------------------------------------------
// TF32 helpers. mma.sync m16n8k8 tf32 (sm_80+) and ldmatrix (sm_75+) are
// plain PTX -- no 'a' gating -- so they survive the compute_103 target.
// ---------------------------------------------------------------------------
__device__ __forceinline__ uint32_t tf32_rna_u(float x) {
    uint32_t u;
    asm("cvt.rna.tf32.f32 %0, %1;" : "=r"(u) : "f"(x));
    return u;
}
__device__ __forceinline__ float tf32_rna(float x) {
    return __uint_as_float(tf32_rna_u(x));
}
__device__ __forceinline__ uint32_t smem_u32(const void* p) {
    uint32_t a;
    asm("{ .reg .u64 t; cvta.to.shared.u64 t, %1; cvt.u32.u64 %0, t; }"
        : "=r"(a) : "l"(p));
    return a;
}

#define LDSM4(r, a) \
    asm volatile("ldmatrix.sync.aligned.m8n8.x4.shared.b16 {%0,%1,%2,%3}, [%4];" \
        : "=r"((r)[0]), "=r"((r)[1]), "=r"((r)[2]), "=r"((r)[3]) : "r"(a))

#define MMA_TF32(c, A, b0, b1) \
    asm volatile("mma.sync.aligned.m16n8k8.row.col.f32.tf32.tf32.f32 " \
        "{%0,%1,%2,%3}, {%4,%5,%6,%7}, {%8,%9}, {%0,%1,%2,%3};" \
        : "+f"((c)[0]), "+f"((c)[1]), "+f"((c)[2]), "+f"((c)[3]) \
        : "r"((A)[0]), "r"((A)[1]), "r"((A)[2]), "r"((A)[3]), \
          "r"(b0), "r"(b1))

// ---------------------------------------------------------------------------
// Kernel 1: GEMM h[m,o] = sum_i X[m,i]*W[o,i] + bias[o], tensor-core tf32,
// fp32-accurate 3-pass split (hi*hi + hi*lo + lo*hi), split ONCE into smem
// (hi/lo tiles), fragments via ldmatrix (LDA=20 -> conflict-free).
// CTA 128(M) x 128(N), 8 warps of 64x32, BK=16 double-buffered.
// 12 LDSM / 48 MMA per warp-k8 (r7 was 8/24) -> L1 pressure per MMA cut.
// Epilogue zeroes g_cur (512 blocks x 64 ints = 32768).
// ---------------------------------------------------------------------------
#define LDA   20                  // smem row stride in floats
#define A_LO  (128 * LDA)
#define B_HI  (256 * LDA)
#define B_LO  (384 * LDA)
#define SSZ   (512 * LDA)         // floats per stage = 10240 (40KB)
#define GEMM_SMEM (2 * SSZ * 4)   // 81920 bytes

__global__ __launch_bounds__(256, 2) void gemm_mma_kernel(const float* __restrict__ X,
                                                          const float* __restrict__ W,
                                                          const float* __restrict__ bias) {
    extern __shared__ __align__(16) float sm[];
    const uint32_t sbase = smem_u32(sm);
    const int tid  = threadIdx.x;
    const int wid  = tid >> 5;
    const int lane = tid & 31;
    const int gid  = lane >> 2;        // group of 4 (epilogue row)
    const int tig  = lane & 3;         // thread in group (epilogue col)
    const int warp_m = wid & 1;        // 2 x 64 rows
    const int warp_n = wid >> 1;       // 4 x 32 cols
    const int bm = blockIdx.x * 128;
    const int bn = blockIdx.y * 128;

    float c[4][4][4] = {};             // 4 m-tiles x 4 n-tiles x 4 accum

    // ldmatrix per-lane row assignments (word offsets within a stage)
    const int a_row_in = ((lane >> 3) & 1) * 8 + (lane & 7);
    const int a_kh     = (lane >> 4) * 4;          // k-half * 4
    int a_off[4], b_off[2];
    #pragma unroll
    for (int mt = 0; mt < 4; mt++)
        a_off[mt] = (warp_m * 64 + mt * 16 + a_row_in) * LDA + a_kh;
    const int b_q   = lane >> 3;
    const int b_kh  = (b_q & 1) * 4;
    const int b_sub = (b_q >> 1) & 1;
    #pragma unroll
    for (int p = 0; p < 2; p++)
        b_off[p] = B_HI + (warp_n * 32 + p * 16 + b_sub * 8 + (lane & 7)) * LDA + b_kh;

    float4 xa[2], wb[2];
    auto loadg = [&](int k0) {
        #pragma unroll
        for (int i = 0; i < 2; i++) {
            const int f = tid + i * 256;           // 0..511
            const int r = f >> 2, k4 = (f & 3) << 2;
            xa[i] = *(const float4*)&X[(size_t)(bm + r) * Dn + k0 + k4];
            wb[i] = *(const float4*)&W[(size_t)(bn + r) * Dn + k0 + k4];
        }
    };
    auto stores = [&](int buf) {       // split once, hi/lo tiles, STS.128
        float* base = sm + buf * SSZ;
        #pragma unroll
        for (int i = 0; i < 2; i++) {
            const int f = tid + i * 256;
            const int r = f >> 2, k4 = (f & 3) << 2;
            float4 h4, l4;
            h4.x = tf32_rna(xa[i].x); l4.x = tf32_rna(xa[i].x - h4.x);
            h4.y = tf32_rna(xa[i].y); l4.y = tf32_rna(xa[i].y - h4.y);
            h4.z = tf32_rna(xa[i].z); l4.z = tf32_rna(xa[i].z - h4.z);
            h4.w = tf32_rna(xa[i].w); l4.w = tf32_rna(xa[i].w - h4.w);
            *(float4*)&base[r * LDA + k4]        = h4;
            *(float4*)&base[A_LO + r * LDA + k4] = l4;
            h4.x = tf32_rna(wb[i].x); l4.x = tf32_rna(wb[i].x - h4.x);
            h4.y = tf32_rna(wb[i].y); l4.y = tf32_rna(wb[i].y - h4.y);
            h4.z = tf32_rna(wb[i].z); l4.z = tf32_rna(wb[i].z - h4.z);
            h4.w = tf32_rna(wb[i].w); l4.w = tf32_rna(wb[i].w - h4.w);
            *(float4*)&base[B_HI + r * LDA + k4] = h4;
            *(float4*)&base[B_LO + r * LDA + k4] = l4;
        }
    };

    loadg(0);
    stores(0);
    __syncthreads();

    #pragma unroll 1
    for (int t = 0; t < Dn / 16; t++) {
        const int buf = t & 1;
        if (t < Dn / 16 - 1) loadg((t + 1) * 16);
        const uint32_t sb = sbase + (uint32_t)buf * (SSZ * 4);

        #pragma unroll
        for (int kk = 0; kk < 2; kk++) {
            const int kc = kk * 8;
            uint32_t bh[2][4], bl[2][4];
            #pragma unroll
            for (int p = 0; p < 2; p++) {
                LDSM4(bh[p], sb + (b_off[p] + kc) * 4);
                LDSM4(bl[p], sb + (b_off[p] + (B_LO - B_HI) + kc) * 4);
            }
            #pragma unroll
            for (int m = 0; m < 4; m++) {          // m-outer keeps A frags short-lived
                uint32_t ah[4], al[4];
                LDSM4(ah, sb + (a_off[m] + kc) * 4);
                LDSM4(al, sb + (a_off[m] + A_LO + kc) * 4);
                #pragma unroll
                for (int n = 0; n < 4; n++) {
                    const int p = n >> 1, o = (n & 1) * 2;
                    MMA_TF32(c[m][n], ah, bh[p][o], bh[p][o + 1]);   // hi*hi
                    MMA_TF32(c[m][n], ah, bl[p][o], bl[p][o + 1]);   // hi*lo
                    MMA_TF32(c[m][n], al, bh[p][o], bh[p][o + 1]);   // lo*hi
                }
            }
        }

        if (t < Dn / 16 - 1) stores(buf ^ 1);
        __syncthreads();
    }

    // Epilogue: bias add, store h (float2 per fragment row-pair)
    #pragma unroll
    for (int m = 0; m < 4; m++) {
        const int r0 = bm + warp_m * 64 + m * 16 + gid;
        #pragma unroll
        for (int n = 0; n < 4; n++) {
            const int cc = bn + warp_n * 32 + n * 8 + 2 * tig;
            const float b0 = bias[cc], b1 = bias[cc + 1];
            *(float2*)&g_h[(size_t)r0 * Dn + cc] =
                make_float2(c[m][n][0] + b0, c[m][n][1] + b1);
            *(float2*)&g_h[(size_t)(r0 + 8) * Dn + cc] =
                make_float2(c[m][n][2] + b0, c[m][n][3] + b1);
        }
    }

    // zero CSR cursors: 512 blocks x 64 ints = 32768
    const int lb = blockIdx.y * 256 + blockIdx.x;   // 0..511
    if (tid < 64) g_cur[lb * 64 + tid] = 0;
}

// ---------------------------------------------------------------------------
// Edge-index dtype sniffing (int64 vs int32): values < 4096, so int64 data has
// all odd int32 words == 0. 16 checks -> misclassification prob ~4096^-16.
// ---------------------------------------------------------------------------
__device__ __forceinline__ bool ei_is_int64(const int* p) {
    int acc = 0;
    #pragma unroll
    for (int i = 0; i < 16; i++) acc |= p[2 * i + 1];
    return acc == 0;
}
__device__ __forceinline__ void load_edge(const void* ei, int b, int e,
                                          bool is64, int& src, int& tgt) {
    if (is64) {
        const long long* base = (const long long*)ei + (size_t)b * 2 * En;
        src = (int)base[e];
        tgt = (int)base[En + e];
    } else {
        const int* base = (const int*)ei + (size_t)b * 2 * En;
        src = base[e];
        tgt = base[En + e];
    }
}

// ---------------------------------------------------------------------------
// Kernel 2: single-pass CSR build. Active edge -> slot in fixed-stride list.
// ---------------------------------------------------------------------------
__global__ __launch_bounds__(256) void edge_kernel(const void* __restrict__ ei,
                                                   const int* __restrict__ nm) {
    const int gid = blockIdx.x * 256 + threadIdx.x;
    if (gid >= Bn * En) return;
    const int b = gid >> 16, e = gid & (En - 1);
    const bool is64 = ei_is_int64((const int*)ei);
    int src, tgt;
    load_edge(ei, b, e, is64, src, tgt);
    if (nm[b * Nn + src] && nm[b * Nn + tgt]) {
        const int row = b * Nn + tgt;
        const int slot = atomicAdd(&g_cur[row], 1);
        if (slot < SLOTS) g_csr[(size_t)row * SLOTS + slot] = src;
    }
}

// ---------------------------------------------------------------------------
// Kernel 3: fused gather + add + LayerNorm + relu + mask. 1 block (256 thr)
// per row; each thread owns one column d. Gather loop unrolled x4 for MLP.
// (exact revert to the version benched at 131.6us)
// ---------------------------------------------------------------------------
__global__ __launch_bounds__(256) void gather_ln_kernel(const float* __restrict__ gamma,
                                                        const float* __restrict__ beta,
                                                        const int* __restrict__ nm,
                                                        float* __restrict__ out) {
    const int row = blockIdx.x;
    const int d   = threadIdx.x;
    const size_t off = (size_t)row * Dn;

    if (nm[row] == 0) {              // block-uniform: output row is exactly zero
        out[off + d] = 0.f;
        return;
    }

    int cnt = g_cur[row];
    cnt = cnt < SLOTS ? cnt : SLOTS;            // memory-safety clamp
    const int* lst = g_csr + (size_t)row * SLOTS;
    const int bbase = (row >> 12) << 12;        // b * Nn
    const float* hb = g_h + (size_t)bbase * Dn + d;

    float a0 = 0.f, a1 = 0.f, a2 = 0.f, a3 = 0.f;
    int i = 0;
    for (; i + 4 <= cnt; i += 4) {              // 4 independent loads in flight
        const int s0 = lst[i], s1 = lst[i + 1], s2 = lst[i + 2], s3 = lst[i + 3];
        a0 += hb[(size_t)s0 * Dn];
        a1 += hb[(size_t)s1 * Dn];
        a2 += hb[(size_t)s2 * Dn];
        a3 += hb[(size_t)s3 * Dn];
    }
    for (; i < cnt; i++) a0 += hb[(size_t)lst[i] * Dn];
    const float agg = (a0 + a1) + (a2 + a3);

    const float y = g_h[off + d] + agg * 0.015625f;   // 1/sqrt(4096)

    __shared__ float s_sum[8], s_sq[8];
    float s = y, q = y * y;
    #pragma unroll
    for (int o = 16; o > 0; o >>= 1) {
        s += __shfl_xor_sync(0xFFFFFFFF, s, o);
        q += __shfl_xor_sync(0xFFFFFFFF, q, o);
    }
    const int wid = d >> 5, lane = d & 31;
    if (lane == 0) { s_sum[wid] = s; s_sq[wid] = q; }
    __syncthreads();
    if (wid == 0) {
        s = (lane < 8) ? s_sum[lane] : 0.f;
        q = (lane < 8) ? s_sq[lane]  : 0.f;
        #pragma unroll
        for (int o = 4; o > 0; o >>= 1) {
            s += __shfl_xor_sync(0xFFFFFFFF, s, o);
            q += __shfl_xor_sync(0xFFFFFFFF, q, o);
        }
        if (lane == 0) { s_sum[0] = s; s_sq[0] = q; }
    }
    __syncthreads();

    const float mu  = s_sum[0] * (1.f / Dn);
    const float var = s_sq[0] * (1.f / Dn) - mu * mu;
    const float r   = rsqrtf(var + 1e-5f);
    const float v   = (y - mu) * r * gamma[d] + beta[d];
    out[off + d] = fmaxf(v, 0.f);
}

// ---------------------------------------------------------------------------
extern "C" void kernel_launch(void* const* d_in, const int* in_sizes, int n_in,
                              void* d_out, int out_size) {
    const float* X     = (const float*)d_in[0];   // (B,N,D)
    const float* W     = (const float*)d_in[1];   // (D,D)
    const float* bias  = (const float*)d_in[2];   // (D,)
    const float* gamma = (const float*)d_in[3];   // (D,)
    const float* beta  = (const float*)d_in[4];   // (D,)
    const void*  ei    = d_in[5];                 // (B,2,E) int32 or int64
    const int*   nm    = (const int*)d_in[6];     // (B,N) int32
    float*       out   = (float*)d_out;           // (B,N,D) f32

    cudaFuncSetAttribute(gemm_mma_kernel,
                         cudaFuncAttributeMaxDynamicSharedMemorySize, GEMM_SMEM);

    dim3 gg(M_TOT / 128, Dn / 128);               // (256, 2)
    gemm_mma_kernel<<<gg, 256, GEMM_SMEM>>>(X, W, bias);  // also zeroes g_cur

    edge_kernel<<<(Bn * En) / 256, 256>>>(ei, nm);

    gather_ln_kernel<<<M_TOT, 256>>>(gamma, beta, nm, out);
}

// round 12
// speedup vs baseline: 1.8391x; 1.3309x over previous
#include <cuda_runtime.h>
#include <cuda_bf16.h>
#include <cstdint>

#define Bn 8
#define Nn 4096
#define En 65536
#define Dn 256
#define M_TOT (Bn*Nn)   // 32768 rows
#define SLOTS 96        // per-target src-list capacity (deg ~ Binom(65536,1/4096), mean 16)

// Scratch (allocation-free rule: __device__ globals)
__device__ float g_h[(size_t)M_TOT * Dn];          // 33.5 MB: h = X W^T + b
__device__ int   g_cur[M_TOT];                     // per-(b,tgt) active-edge count
__device__ int   g_csr[(size_t)M_TOT * SLOTS];     // src lists, fixed stride

// ---------------------------------------------------------------------------
// BF16 helpers. mma.sync m16n8k16 bf16 (sm_80+) and ldmatrix (sm_75+) are
// plain PTX -- no 'a' gating -- so they survive the compute_103 target.
// ---------------------------------------------------------------------------
__device__ __forceinline__ uint32_t smem_u32(const void* p) {
    uint32_t a;
    asm("{ .reg .u64 t; cvta.to.shared.u64 t, %1; cvt.u32.u64 %0, t; }"
        : "=r"(a) : "l"(p));
    return a;
}
// pack two floats to bf16x2: low half <- x_lo (element k), high half <- x_hi (k+1)
__device__ __forceinline__ uint32_t bf16x2_pack(float x_lo, float x_hi) {
    uint32_t r;
    asm("cvt.rn.bf16x2.f32 %0, %1, %2;" : "=r"(r) : "f"(x_hi), "f"(x_lo));
    return r;
}

#define LDSM4(r, a) \
    asm volatile("ldmatrix.sync.aligned.m8n8.x4.shared.b16 {%0,%1,%2,%3}, [%4];" \
        : "=r"((r)[0]), "=r"((r)[1]), "=r"((r)[2]), "=r"((r)[3]) : "r"(a))

#define MMA_BF16(c, A, b0, b1) \
    asm volatile("mma.sync.aligned.m16n8k16.row.col.f32.bf16.bf16.f32 " \
        "{%0,%1,%2,%3}, {%4,%5,%6,%7}, {%8,%9}, {%0,%1,%2,%3};" \
        : "+f"((c)[0]), "+f"((c)[1]), "+f"((c)[2]), "+f"((c)[3]) \
        : "r"((A)[0]), "r"((A)[1]), "r"((A)[2]), "r"((A)[3]), \
          "r"(b0), "r"(b1))

// split float4 (4 consecutive k) -> hi pair-of-bf16x2 and lo pair-of-bf16x2
__device__ __forceinline__ void split4_bf16(const float4 v, uint2& hi, uint2& lo) {
    const uint32_t h0 = bf16x2_pack(v.x, v.y);
    const uint32_t h1 = bf16x2_pack(v.z, v.w);
    const float f0 = __uint_as_float(h0 << 16);          // bf16(v.x) as f32
    const float f1 = __uint_as_float(h0 & 0xFFFF0000u);  // bf16(v.y)
    const float f2 = __uint_as_float(h1 << 16);
    const float f3 = __uint_as_float(h1 & 0xFFFF0000u);
    hi.x = h0; hi.y = h1;
    lo.x = bf16x2_pack(v.x - f0, v.y - f1);
    lo.y = bf16x2_pack(v.z - f2, v.w - f3);
}

// ---------------------------------------------------------------------------
// Kernel 1: GEMM h[m,o] = sum_i X[m,i]*W[o,i] + bias[o], tensor-core bf16,
// fp32-accurate 3-pass 2-way-bf16 split (hi*hi + hi*lo + lo*hi ~ 2^-16 rel),
// split ONCE into smem (bf16 hi/lo tiles), fragments via ldmatrix.
// CTA 128(M) x 128(N), 8 warps of 64x32, BK=16 double-buffered.
// k16 MMA -> HALF the MMA/LDSM/STS count of the r11 tf32-k8 version.
// Row stride 24 halves (48B): 8-row ldmatrix segments conflict-free.
// Epilogue zeroes g_cur (512 blocks x 64 ints = 32768).
// ---------------------------------------------------------------------------
#define AHI_H 0                    // offsets in halves (uint16 units)
#define ALO_H 3072                 // 128 rows * 24
#define BHI_H 6144
#define BLO_H 9216
#define SSZ_B (12288 * 2)          // stage bytes = 24KB
#define GEMM_SMEM (2 * SSZ_B)      // 49152 bytes

__global__ __launch_bounds__(256, 2) void gemm_mma_kernel(const float* __restrict__ X,
                                                          const float* __restrict__ W,
                                                          const float* __restrict__ bias) {
    extern __shared__ __align__(16) char smc[];
    const uint32_t sbase = smem_u32(smc);
    const int tid  = threadIdx.x;
    const int wid  = tid >> 5;
    const int lane = tid & 31;
    const int gid  = lane >> 2;        // group of 4 (epilogue row)
    const int tig  = lane & 3;         // thread in group (epilogue col)
    const int warp_m = wid & 1;        // 2 x 64 rows
    const int warp_n = wid >> 1;       // 4 x 32 cols
    const int bm = blockIdx.x * 128;
    const int bn = blockIdx.y * 128;

    float c[4][4][4] = {};             // 4 m-tiles x 4 n-tiles x 4 accum

    // ldmatrix per-lane assignments (offsets in halves within a stage)
    // A m16k16: groups 0-7:m0-7/k0-7, 8-15:m8-15/k0-7, 16-23:m0-7/k8-15, 24-31:m8-15/k8-15
    const int a_row_in = ((lane >> 3) & 1) * 8 + (lane & 7);
    const int a_kh     = (lane >> 4) * 8;          // k-half * 8 halves (16B)
    int a_off[4], b_off[2];
    #pragma unroll
    for (int mt = 0; mt < 4; mt++)
        a_off[mt] = AHI_H + (warp_m * 64 + mt * 16 + a_row_in) * 24 + a_kh;
    // B n16(k16) pair: groups 0-7:n0-7/k0-7, 8-15:n0-7/k8-15, 16-23:n8-15/k0-7, 24-31:n8-15/k8-15
    const int b_q   = lane >> 3;
    const int b_kh  = (b_q & 1) * 8;
    const int b_sub = (b_q >> 1) & 1;
    #pragma unroll
    for (int p = 0; p < 2; p++)
        b_off[p] = BHI_H + (warp_n * 32 + p * 16 + b_sub * 8 + (lane & 7)) * 24 + b_kh;

    float4 xa[2], wb[2];
    auto loadg = [&](int k0) {
        #pragma unroll
        for (int i = 0; i < 2; i++) {
            const int f = tid + i * 256;           // 0..511
            const int r = f >> 2, k4 = (f & 3) << 2;
            xa[i] = *(const float4*)&X[(size_t)(bm + r) * Dn + k0 + k4];
            wb[i] = *(const float4*)&W[(size_t)(bn + r) * Dn + k0 + k4];
        }
    };
    auto stores = [&](int buf) {       // split once into bf16 hi/lo, STS.64
        char* base = smc + buf * SSZ_B;
        #pragma unroll
        for (int i = 0; i < 2; i++) {
            const int f = tid + i * 256;
            const int r = f >> 2, k4 = (f & 3) << 2;
            const int ro = (r * 24 + k4) * 2;      // byte offset within tile
            uint2 hi, lo;
            split4_bf16(xa[i], hi, lo);
            *(uint2*)(base + AHI_H * 2 + ro) = hi;
            *(uint2*)(base + ALO_H * 2 + ro) = lo;
            split4_bf16(wb[i], hi, lo);
            *(uint2*)(base + BHI_H * 2 + ro) = hi;
            *(uint2*)(base + BLO_H * 2 + ro) = lo;
        }
    };

    loadg(0);
    stores(0);
    __syncthreads();

    #pragma unroll 1
    for (int t = 0; t < Dn / 16; t++) {
        const int buf = t & 1;
        if (t < Dn / 16 - 1) loadg((t + 1) * 16);
        const uint32_t sb = sbase + (uint32_t)buf * SSZ_B;

        uint32_t bh[2][4], bl[2][4];
        #pragma unroll
        for (int p = 0; p < 2; p++) {
            LDSM4(bh[p], sb + (uint32_t)b_off[p] * 2);
            LDSM4(bl[p], sb + (uint32_t)(b_off[p] + (BLO_H - BHI_H)) * 2);
        }
        #pragma unroll
        for (int m = 0; m < 4; m++) {              // m-outer keeps A frags short-lived
            uint32_t ah[4], al[4];
            LDSM4(ah, sb + (uint32_t)a_off[m] * 2);
            LDSM4(al, sb + (uint32_t)(a_off[m] + (ALO_H - AHI_H)) * 2);
            #pragma unroll
            for (int n = 0; n < 4; n++) {
                const int p = n >> 1, o = (n & 1) * 2;
                MMA_BF16(c[m][n], ah, bh[p][o], bh[p][o + 1]);   // hi*hi
                MMA_BF16(c[m][n], ah, bl[p][o], bl[p][o + 1]);   // hi*lo
                MMA_BF16(c[m][n], al, bh[p][o], bh[p][o + 1]);   // lo*hi
            }
        }

        if (t < Dn / 16 - 1) stores(buf ^ 1);
        __syncthreads();
    }

    // Epilogue: bias add, store h (float2 per fragment row-pair)
    #pragma unroll
    for (int m = 0; m < 4; m++) {
        const int r0 = bm + warp_m * 64 + m * 16 + gid;
        #pragma unroll
        for (int n = 0; n < 4; n++) {
            const int cc = bn + warp_n * 32 + n * 8 + 2 * tig;
            const float b0 = bias[cc], b1 = bias[cc + 1];
            *(float2*)&g_h[(size_t)r0 * Dn + cc] =
                make_float2(c[m][n][0] + b0, c[m][n][1] + b1);
            *(float2*)&g_h[(size_t)(r0 + 8) * Dn + cc] =
                make_float2(c[m][n][2] + b0, c[m][n][3] + b1);
        }
    }

    // zero CSR cursors: 512 blocks x 64 ints = 32768
    const int lb = blockIdx.y * 256 + blockIdx.x;   // 0..511
    if (tid < 64) g_cur[lb * 64 + tid] = 0;
}

// ---------------------------------------------------------------------------
// Edge-index dtype sniffing (int64 vs int32): values < 4096, so int64 data has
// all odd int32 words == 0. 16 checks -> misclassification prob ~4096^-16.
// ---------------------------------------------------------------------------
__device__ __forceinline__ bool ei_is_int64(const int* p) {
    int acc = 0;
    #pragma unroll
    for (int i = 0; i < 16; i++) acc |= p[2 * i + 1];
    return acc == 0;
}
__device__ __forceinline__ void load_edge(const void* ei, int b, int e,
                                          bool is64, int& src, int& tgt) {
    if (is64) {
        const long long* base = (const long long*)ei + (size_t)b * 2 * En;
        src = (int)base[e];
        tgt = (int)base[En + e];
    } else {
        const int* base = (const int*)ei + (size_t)b * 2 * En;
        src = base[e];
        tgt = base[En + e];
    }
}

// ---------------------------------------------------------------------------
// Kernel 2: single-pass CSR build. Active edge -> slot in fixed-stride list.
// ---------------------------------------------------------------------------
__global__ __launch_bounds__(256) void edge_kernel(const void* __restrict__ ei,
                                                   const int* __restrict__ nm) {
    const int gid = blockIdx.x * 256 + threadIdx.x;
    if (gid >= Bn * En) return;
    const int b = gid >> 16, e = gid & (En - 1);
    const bool is64 = ei_is_int64((const int*)ei);
    int src, tgt;
    load_edge(ei, b, e, is64, src, tgt);
    if (nm[b * Nn + src] && nm[b * Nn + tgt]) {
        const int row = b * Nn + tgt;
        const int slot = atomicAdd(&g_cur[row], 1);
        if (slot < SLOTS) g_csr[(size_t)row * SLOTS + slot] = src;
    }
}

// ---------------------------------------------------------------------------
// Kernel 3: fused gather + add + LayerNorm + relu + mask. 1 block (256 thr)
// per row; each thread owns one column d. Gather loop unrolled x4 for MLP.
// ---------------------------------------------------------------------------
__global__ __launch_bounds__(256) void gather_ln_kernel(const float* __restrict__ gamma,
                                                        const float* __restrict__ beta,
                                                        const int* __restrict__ nm,
                                                        float* __restrict__ out) {
    const int row = blockIdx.x;
    const int d   = threadIdx.x;
    const size_t off = (size_t)row * Dn;

    if (nm[row] == 0) {              // block-uniform: output row is exactly zero
        out[off + d] = 0.f;
        return;
    }

    int cnt = g_cur[row];
    cnt = cnt < SLOTS ? cnt : SLOTS;            // memory-safety clamp
    const int* lst = g_csr + (size_t)row * SLOTS;
    const int bbase = (row >> 12) << 12;        // b * Nn
    const float* hb = g_h + (size_t)bbase * Dn + d;

    float a0 = 0.f, a1 = 0.f, a2 = 0.f, a3 = 0.f;
    int i = 0;
    for (; i + 4 <= cnt; i += 4) {              // 4 independent loads in flight
        const int s0 = lst[i], s1 = lst[i + 1], s2 = lst[i + 2], s3 = lst[i + 3];
        a0 += hb[(size_t)s0 * Dn];
        a1 += hb[(size_t)s1 * Dn];
        a2 += hb[(size_t)s2 * Dn];
        a3 += hb[(size_t)s3 * Dn];
    }
    for (; i < cnt; i++) a0 += hb[(size_t)lst[i] * Dn];
    const float agg = (a0 + a1) + (a2 + a3);

    const float y = g_h[off + d] + agg * 0.015625f;   // 1/sqrt(4096)

    __shared__ float s_sum[8], s_sq[8];
    float s = y, q = y * y;
    #pragma unroll
    for (int o = 16; o > 0; o >>= 1) {
        s += __shfl_xor_sync(0xFFFFFFFF, s, o);
        q += __shfl_xor_sync(0xFFFFFFFF, q, o);
    }
    const int wid = d >> 5, lane = d & 31;
    if (lane == 0) { s_sum[wid] = s; s_sq[wid] = q; }
    __syncthreads();
    if (wid == 0) {
        s = (lane < 8) ? s_sum[lane] : 0.f;
        q = (lane < 8) ? s_sq[lane]  : 0.f;
        #pragma unroll
        for (int o = 4; o > 0; o >>= 1) {
            s += __shfl_xor_sync(0xFFFFFFFF, s, o);
            q += __shfl_xor_sync(0xFFFFFFFF, q, o);
        }
        if (lane == 0) { s_sum[0] = s; s_sq[0] = q; }
    }
    __syncthreads();

    const float mu  = s_sum[0] * (1.f / Dn);
    const float var = s_sq[0] * (1.f / Dn) - mu * mu;
    const float r   = rsqrtf(var + 1e-5f);
    const float v   = (y - mu) * r * gamma[d] + beta[d];
    out[off + d] = fmaxf(v, 0.f);
}

// ---------------------------------------------------------------------------
extern "C" void kernel_launch(void* const* d_in, const int* in_sizes, int n_in,
                              void* d_out, int out_size) {
    const float* X     = (const float*)d_in[0];   // (B,N,D)
    const float* W     = (const float*)d_in[1];   // (D,D)
    const float* bias  = (const float*)d_in[2];   // (D,)
    const float* gamma = (const float*)d_in[3];   // (D,)
    const float* beta  = (const float*)d_in[4];   // (D,)
    const void*  ei    = d_in[5];                 // (B,2,E) int32 or int64
    const int*   nm    = (const int*)d_in[6];     // (B,N) int32
    float*       out   = (float*)d_out;           // (B,N,D) f32

    cudaFuncSetAttribute(gemm_mma_kernel,
                         cudaFuncAttributeMaxDynamicSharedMemorySize, GEMM_SMEM);

    dim3 gg(M_TOT / 128, Dn / 128);               // (256, 2)
    gemm_mma_kernel<<<gg, 256, GEMM_SMEM>>>(X, W, bias);  // also zeroes g_cur

    edge_kernel<<<(Bn * En) / 256, 256>>>(ei, nm);

    gather_ln_kernel<<<M_TOT, 256>>>(gamma, beta, nm, out);
}